// round 15
// baseline (speedup 1.0000x reference)
#include <cuda_runtime.h>
#include <cstdint>

#define HH 8
#define DD 1024
#define SS 1024
#define MIDD 2048
#define SOUT 512

typedef long long ll;

// ---------------- scratch (device globals; no allocation allowed) ----------
// element format: one uint32 per element = [hi_bf16 (low 2B) | lo_bf16 (hi 2B)]
// planar format: per row of C elements: C/2 hi bf16x2-pair words (permuted
//   within each k16 block as [p0 p4 p1 p5 p2 p6 p3 p7]), then C/2 lo words.
__device__ uint32_t p_qkv [3ll * DD * SS];             // planar (q,d,s)
__device__ uint32_t p_qkv2[3ll * DD * SS];             // planar: q2, enc_k, enc_v
__device__ uint32_t p_z[3ll * HH * DD * MIDD];         // planar (q,h,d,m)
__device__ uint32_t p_s[(ll)HH * 3 * DD * SS];         // element (h,q,d,s)
__device__ uint32_t p_bm[(ll)HH * SS * SS];            // element
__device__ uint32_t p_att[(ll)HH * DD * SS];           // element (h,d,t)
__device__ uint32_t p_y[(ll)SS * MIDD];                // planar
__device__ uint32_t p_h[(ll)DD * SS];                  // element
__device__ uint32_t p_x1[(ll)DD * MIDD];               // planar
__device__ uint32_t p_x2[(ll)DD * SOUT];               // planar
__device__ float    g_m[(ll)DD * SS];
// packed inputs / weights
__device__ uint32_t p_inp [(ll)DD * SS];               // element (used transposed)
__device__ uint32_t p_wqkv1[3ll * DD * DD];            // planar
__device__ uint32_t p_wqkv2[(ll)DD * DD];              // planar
__device__ uint32_t p_W1a[(ll)HH * 3 * MIDD * SS];     // planar
__device__ uint32_t p_W2a[(ll)HH * 3 * SS * MIDD];     // planar
__device__ uint32_t p_W1b[(ll)HH * 3 * MIDD * SS];
__device__ uint32_t p_W2b[(ll)HH * 3 * SS * MIDD];
__device__ uint32_t p_c1w1[(ll)MIDD * HH * DD];        // planar
__device__ uint32_t p_c2w1[(ll)MIDD * HH * DD];
__device__ uint32_t p_c1w2[(ll)DD * MIDD];             // planar
__device__ uint32_t p_c2w2[(ll)DD * MIDD];
__device__ uint32_t p_l1w1[(ll)MIDD * SS];             // planar
__device__ uint32_t p_l1w2[(ll)SOUT * MIDD];
__device__ uint32_t p_l2w1[(ll)MIDD * SOUT];
__device__ uint32_t p_l2w2[(ll)SOUT * MIDD];

// ---------------- PTX helpers (base sm_103 features only) -------------------
__device__ __forceinline__ uint32_t smem_u32(const void* p) {
    uint32_t a;
    asm("{ .reg .u64 t; cvta.to.shared.u64 t, %1; cvt.u32.u64 %0, t; }"
        : "=r"(a) : "l"(p));
    return a;
}
__device__ __forceinline__ void cpa16(uint32_t dst, const void* src) {
    asm volatile("cp.async.cg.shared.global [%0], [%1], 16;"
                 :: "r"(dst), "l"(src) : "memory");
}
__device__ __forceinline__ void cpa4(uint32_t dst, const void* src) {
    asm volatile("cp.async.ca.shared.global [%0], [%1], 4;"
                 :: "r"(dst), "l"(src) : "memory");
}
__device__ __forceinline__ void cp_commit() {
    asm volatile("cp.async.commit_group;" ::: "memory");
}
template<int NG>
__device__ __forceinline__ void cp_wait() {
    asm volatile("cp.async.wait_group %0;" :: "n"(NG) : "memory");
}
__device__ __forceinline__ uint32_t prmtb(uint32_t a, uint32_t b, uint32_t s) {
    uint32_t r;
    asm("prmt.b32 %0, %1, %2, %3;" : "=r"(r) : "r"(a), "r"(b), "r"(s));
    return r;
}

// bf16 split of a float2 -> hi bf16x2 pair word + lo (residual) pair word
template<bool RELU>
__device__ __forceinline__ void splitp(float2 v, uint32_t& hp, uint32_t& lp) {
    if (RELU) { v.x = fmaxf(v.x, 0.f); v.y = fmaxf(v.y, 0.f); }
    asm("cvt.rn.bf16x2.f32 %0, %1, %2;" : "=r"(hp) : "f"(v.y), "f"(v.x));
    const float hx = __uint_as_float(hp << 16);
    const float hy = __uint_as_float(hp & 0xffff0000u);
    asm("cvt.rn.bf16x2.f32 %0, %1, %2;" : "=r"(lp) : "f"(v.y - hy), "f"(v.x - hx));
}
// element-format pack: two element words [hi|lo] each
template<bool RELU>
__device__ __forceinline__ void pack2(float2 v, uint32_t& w0, uint32_t& w1) {
    uint32_t hp, lp;
    splitp<RELU>(v, hp, lp);
    w0 = prmtb(hp, lp, 0x5410);
    w1 = prmtb(hp, lp, 0x7632);
}
// element-format fragment: two adjacent element words -> hi pair + lo pair
__device__ __forceinline__ void fragp(const uint32_t* p, uint32_t& hi, uint32_t& lo) {
    const uint2 e = *(const uint2*)p;
    hi = prmtb(e.x, e.y, 0x5410);
    lo = prmtb(e.x, e.y, 0x7632);
}
// planar position of pair p within a row's hi (or lo) section
__device__ __forceinline__ int ppos(int c) {        // c = even element column
    const int q = (c >> 1) & 7;
    return ((c >> 4) << 3) + 2 * (q & 3) + (q >> 2);
}

__device__ __forceinline__ void mma16(float* d, const uint32_t* a, const uint32_t* b) {
    asm volatile(
        "mma.sync.aligned.m16n8k16.row.col.f32.bf16.bf16.f32 "
        "{%0,%1,%2,%3}, {%4,%5,%6,%7}, {%8,%9}, {%0,%1,%2,%3};"
        : "+f"(d[0]), "+f"(d[1]), "+f"(d[2]), "+f"(d[3])
        : "r"(a[0]), "r"(a[1]), "r"(a[2]), "r"(a[3]), "r"(b[0]), "r"(b[1]));
}

// ---------------- pack kernels (ILP=4) ---------------------------------------
template<bool RELU>
__global__ __launch_bounds__(256) void pack_elem(
    const float4* __restrict__ src, uint4* __restrict__ dst, int n4)
{
    const int base = blockIdx.x * 1024 + threadIdx.x;
    float4 v[4];
    #pragma unroll
    for (int j = 0; j < 4; j++) {
        const int i = base + j * 256;
        if (i < n4) v[j] = src[i];
    }
    #pragma unroll
    for (int j = 0; j < 4; j++) {
        const int i = base + j * 256;
        if (i < n4) {
            uint4 o;
            pack2<RELU>(make_float2(v[j].x, v[j].y), o.x, o.y);
            pack2<RELU>(make_float2(v[j].z, v[j].w), o.z, o.w);
            dst[i] = o;
        }
    }
}

template<bool RELU>
__global__ __launch_bounds__(256) void pack_planar(
    const float* __restrict__ src, uint32_t* __restrict__ dst, int C, int n4)
{
    const int base = blockIdx.x * 1024 + threadIdx.x;
    #pragma unroll
    for (int j = 0; j < 4; j++) {
        const int i = base + j * 256;
        if (i >= n4) continue;
        const ll idx = (ll)i * 4;
        const int c = (int)(idx % C);
        const ll rowbase = idx - c;
        const float4 v = *(const float4*)(src + idx);
        uint32_t h0, l0, h1, l1;
        splitp<RELU>(make_float2(v.x, v.y), h0, l0);
        splitp<RELU>(make_float2(v.z, v.w), h1, l1);
        const int q0 = ppos(c), q1 = ppos(c + 2);
        const int half = C >> 1;
        dst[rowbase + q0]        = h0;
        dst[rowbase + q1]        = h1;
        dst[rowbase + half + q0] = l0;
        dst[rowbase + half + q1] = l1;
    }
}

// ---------------- packed bf16x3 mma.sync GEMM -------------------------------
// D[m][n] = sum_k a[m][k] * b[n][k].
//   FA/FB: 0 = planar row-major, 1 = element row-major, 2 = element transposed.
//   EP: 0 fp32, 1 fp32+tanh, 2 element packed, 3 element packed+relu,
//       4 planar packed, 5 planar packed+relu.
// Batch decode: h = bz & 7, q = bz >> 3. 256 threads (8 warps, 2x4 grid).

#define STR     40
#define TILE_W  (128 * STR)
#define STAGE_B (TILE_W * 4)
#define SMEM_DYN (4 * STAGE_B)

template<int FA, int FB, int EP>
__global__ __launch_bounds__(256, 2) void gemm_p(
    const uint32_t* __restrict__ Ag, const uint32_t* __restrict__ Bg, void* Cg,
    int M, int N, int K, ll sA, ll sB, ll sC, ll sA2, ll sB2, ll sC2)
{
    extern __shared__ __align__(16) uint32_t smem[];
    const uint32_t sb = smem_u32(smem);

    const int bz = blockIdx.z;
    const int hz = bz & 7, qz = bz >> 3;
    const uint32_t* A = Ag + (ll)hz * sA + (ll)qz * sA2;
    const uint32_t* B = Bg + (ll)hz * sB + (ll)qz * sB2;
    const ll coff = (ll)hz * sC + (ll)qz * sC2;
    const int m0 = blockIdx.y * 128;
    const int n0 = blockIdx.x * 128;

    const int tid = threadIdx.x;
    const int wid = tid >> 5, lid = tid & 31;
    const int wm = wid >> 2, wn = wid & 3;
    const int g = lid >> 2, tg = lid & 3;

    float acc[4][4][4];
    #pragma unroll
    for (int mi = 0; mi < 4; mi++)
        #pragma unroll
        for (int ni = 0; ni < 4; ni++)
            #pragma unroll
            for (int r = 0; r < 4; r++) acc[mi][ni][r] = 0.f;

    auto issue = [&](int t) {
        const int st = t & 1;
        const uint32_t abase = sb + (uint32_t)(st * 2) * STAGE_B;
        const uint32_t bbase = abase + STAGE_B;
        const int k0 = t << 5;
        if (FA == 0) {
            #pragma unroll
            for (int i = 0; i < 4; i++) {
                int idx = tid + i * 256;
                int r = idx >> 3, ch = idx & 7, pl = ch >> 2, cc = ch & 3;
                cpa16(abase + (uint32_t)(r * STR + pl * 16 + cc * 4) * 4,
                      A + (ll)(m0 + r) * K + (ll)pl * (K >> 1) + (k0 >> 1) + cc * 4);
            }
        } else if (FA == 1) {
            #pragma unroll
            for (int i = 0; i < 4; i++) {
                int idx = tid + i * 256;
                int r = idx >> 3, kq = (idx & 7) << 2;
                cpa16(abase + (uint32_t)(r * STR + kq) * 4,
                      A + (ll)(m0 + r) * K + k0 + kq);
            }
        } else {
            #pragma unroll
            for (int i = 0; i < 16; i++) {
                int idx = tid + i * 256;
                int m = idx & 127, k = idx >> 7;
                cpa4(abase + (uint32_t)(m * STR + k) * 4,
                     A + (ll)(k0 + k) * M + m0 + m);
            }
        }
        if (FB == 0) {
            #pragma unroll
            for (int i = 0; i < 4; i++) {
                int idx = tid + i * 256;
                int r = idx >> 3, ch = idx & 7, pl = ch >> 2, cc = ch & 3;
                cpa16(bbase + (uint32_t)(r * STR + pl * 16 + cc * 4) * 4,
                      B + (ll)(n0 + r) * K + (ll)pl * (K >> 1) + (k0 >> 1) + cc * 4);
            }
        } else if (FB == 1) {
            #pragma unroll
            for (int i = 0; i < 4; i++) {
                int idx = tid + i * 256;
                int r = idx >> 3, kq = (idx & 7) << 2;
                cpa16(bbase + (uint32_t)(r * STR + kq) * 4,
                      B + (ll)(n0 + r) * K + k0 + kq);
            }
        } else {
            #pragma unroll
            for (int i = 0; i < 16; i++) {
                int idx = tid + i * 256;
                int n = idx & 127, k = idx >> 7;
                cpa4(bbase + (uint32_t)(n * STR + k) * 4,
                     B + (ll)(k0 + k) * N + n0 + n);
            }
        }
    };

    const int T = K >> 5;
    issue(0);
    cp_commit();

    for (int t = 0; t < T; t++) {
        if (t + 1 < T) { issue(t + 1); cp_commit(); cp_wait<1>(); }
        else           { cp_wait<0>(); }
        __syncthreads();

        const uint32_t* As = smem + (t & 1) * 2 * TILE_W;
        const uint32_t* Bs = As + TILE_W;

        #pragma unroll
        for (int ks = 0; ks < 2; ks++) {
            uint32_t bh[4][2], bl[4][2];
            #pragma unroll
            for (int ni = 0; ni < 4; ni++) {
                const int row = wn * 32 + ni * 8 + g;
                if (FB == 0) {
                    const uint32_t* p = Bs + row * STR + ks * 8 + 2 * tg;
                    const uint2 h = *(const uint2*)p;
                    const uint2 l = *(const uint2*)(p + 16);
                    bh[ni][0] = h.x; bh[ni][1] = h.y;
                    bl[ni][0] = l.x; bl[ni][1] = l.y;
                } else {
                    const uint32_t* p = Bs + row * STR + ks * 16 + 2 * tg;
                    fragp(p,     bh[ni][0], bl[ni][0]);
                    fragp(p + 8, bh[ni][1], bl[ni][1]);
                }
            }
            #pragma unroll
            for (int mi = 0; mi < 4; mi++) {
                uint32_t ah[4], al[4];
                const int row = wm * 64 + mi * 16 + g;
                if (FA == 0) {
                    const uint32_t* p = As + row * STR + ks * 8 + 2 * tg;
                    const uint2 h0 = *(const uint2*)p;
                    const uint2 l0 = *(const uint2*)(p + 16);
                    const uint2 h1 = *(const uint2*)(p + 8 * STR);
                    const uint2 l1 = *(const uint2*)(p + 8 * STR + 16);
                    ah[0] = h0.x; ah[1] = h1.x; ah[2] = h0.y; ah[3] = h1.y;
                    al[0] = l0.x; al[1] = l1.x; al[2] = l0.y; al[3] = l1.y;
                } else {
                    const uint32_t* p = As + row * STR + ks * 16 + 2 * tg;
                    fragp(p,               ah[0], al[0]);
                    fragp(p + 8 * STR,     ah[1], al[1]);
                    fragp(p + 8,           ah[2], al[2]);
                    fragp(p + 8 * STR + 8, ah[3], al[3]);
                }
                #pragma unroll
                for (int ni = 0; ni < 4; ni++) {
                    mma16(acc[mi][ni], ah, bh[ni]);
                    mma16(acc[mi][ni], ah, bl[ni]);
                    mma16(acc[mi][ni], al, bh[ni]);
                }
            }
        }
        __syncthreads();
    }

    // ---- epilogue ----
    #pragma unroll
    for (int mi = 0; mi < 4; mi++) {
        #pragma unroll
        for (int ni = 0; ni < 4; ni++) {
            const int r0 = m0 + wm * 64 + mi * 16 + g;
            const int c  = n0 + wn * 32 + ni * 8 + 2 * tg;
            float2 v0 = make_float2(acc[mi][ni][0], acc[mi][ni][1]);
            float2 v1 = make_float2(acc[mi][ni][2], acc[mi][ni][3]);
            if (EP <= 1) {
                float* C = (float*)Cg + coff;
                if (EP == 1) {
                    v0.x = tanhf(v0.x); v0.y = tanhf(v0.y);
                    v1.x = tanhf(v1.x); v1.y = tanhf(v1.y);
                }
                *(float2*)(C + (ll)r0 * N + c)       = v0;
                *(float2*)(C + (ll)(r0 + 8) * N + c) = v1;
            } else if (EP <= 3) {
                uint32_t* C = (uint32_t*)Cg + coff;
                uint2 w0, w1;
                pack2<EP == 3>(v0, w0.x, w0.y);
                pack2<EP == 3>(v1, w1.x, w1.y);
                *(uint2*)(C + (ll)r0 * N + c)       = w0;
                *(uint2*)(C + (ll)(r0 + 8) * N + c) = w1;
            } else {
                uint32_t* C = (uint32_t*)Cg + coff;
                const int pos  = ppos(c);
                const int half = N >> 1;
                uint32_t h0, l0, h1, l1;
                splitp<EP == 5>(v0, h0, l0);
                splitp<EP == 5>(v1, h1, l1);
                C[(ll)r0 * N + pos]              = h0;
                C[(ll)r0 * N + half + pos]       = l0;
                C[(ll)(r0 + 8) * N + pos]        = h1;
                C[(ll)(r0 + 8) * N + half + pos] = l1;
            }
        }
    }
}

// ---------------- fused residual-add + LayerNorm -> element packed -----------
template<bool RELU>
__global__ __launch_bounds__(256) void add_ln_k(
    const float* __restrict__ x, const float* __restrict__ m,
    const float* __restrict__ g, const float* __restrict__ b,
    uint32_t* __restrict__ o)
{
    const int row = blockIdx.x;
    const ll off = (ll)row * SS;
    float2 v[2];
    float sum = 0.f, sq = 0.f;
    #pragma unroll
    for (int j = 0; j < 2; j++) {
        int i2 = threadIdx.x * 2 + j * 512;
        float2 xv = *(const float2*)(x + off + i2);
        float2 mv = *(const float2*)(m + off + i2);
        v[j] = make_float2(xv.x + mv.x, xv.y + mv.y);
        sum += v[j].x + v[j].y;
        sq  += v[j].x * v[j].x + v[j].y * v[j].y;
    }
    #pragma unroll
    for (int o2 = 16; o2; o2 >>= 1) {
        sum += __shfl_xor_sync(0xffffffffu, sum, o2);
        sq  += __shfl_xor_sync(0xffffffffu, sq,  o2);
    }
    __shared__ float rs[8], rq[8];
    const int w = threadIdx.x >> 5, l = threadIdx.x & 31;
    if (l == 0) { rs[w] = sum; rq[w] = sq; }
    __syncthreads();
    if (w == 0) {
        float s2 = (l < 8) ? rs[l] : 0.f;
        float q2 = (l < 8) ? rq[l] : 0.f;
        #pragma unroll
        for (int o2 = 4; o2; o2 >>= 1) {
            s2 += __shfl_xor_sync(0xffffffffu, s2, o2);
            q2 += __shfl_xor_sync(0xffffffffu, q2, o2);
        }
        if (l == 0) { rs[0] = s2; rq[0] = q2; }
    }
    __syncthreads();
    const float mu  = rs[0] * (1.f / SS);
    const float var = rq[0] * (1.f / SS) - mu * mu;
    const float inv = rsqrtf(var + 1e-6f);
    #pragma unroll
    for (int j = 0; j < 2; j++) {
        int i2 = threadIdx.x * 2 + j * 512;
        float2 gv = *(const float2*)(g + i2);
        float2 bv = *(const float2*)(b + i2);
        float2 t = make_float2((v[j].x - mu) * inv * gv.x + bv.x,
                               (v[j].y - mu) * inv * gv.y + bv.y);
        uint2 wo;
        pack2<RELU>(t, wo.x, wo.y);
        *(uint2*)(o + off + i2) = wo;
    }
}

// ---------------- host orchestration ----------------------------------------
extern "C" void kernel_launch(void* const* d_in, const int* in_sizes, int n_in,
                              void* d_out, int out_size)
{
    const float* inp    = (const float*)d_in[0];
    const float* enc_k  = (const float*)d_in[1];
    const float* enc_v  = (const float*)d_in[2];
    const float* w_qkv1 = (const float*)d_in[3];
    const float* w_qkv2 = (const float*)d_in[4];
    const float* mh1_W1 = (const float*)d_in[5];
    const float* mh1_W2 = (const float*)d_in[6];
    const float* mh2_W1 = (const float*)d_in[7];
    const float* mh2_W2 = (const float*)d_in[8];
    const float* c1_w1  = (const float*)d_in[9];
    const float* c1_w2  = (const float*)d_in[10];
    const float* c2_w1  = (const float*)d_in[11];
    const float* c2_w2  = (const float*)d_in[12];
    const float* l1_w1  = (const float*)d_in[13];
    const float* l1_w2  = (const float*)d_in[14];
    const float* l2_w1  = (const float*)d_in[15];
    const float* l2_w2  = (const float*)d_in[16];
    const float* gamma  = (const float*)d_in[17];
    const float* beta   = (const float*)d_in[18];
    float* out = (float*)d_out;

    uint32_t *qkv, *qkv2, *z, *s, *bm, *att, *y, *hb, *x1, *x2;
    uint32_t *pinp, *pw1, *pw2;
    uint32_t *W1a, *W2a, *W1b, *W2b, *c1a, *c2a, *c1b, *c2b;
    uint32_t *lw11, *lw12, *lw21, *lw22;
    float* mb;
    cudaGetSymbolAddress((void**)&qkv,  p_qkv);
    cudaGetSymbolAddress((void**)&qkv2, p_qkv2);
    cudaGetSymbolAddress((void**)&z,    p_z);
    cudaGetSymbolAddress((void**)&s,    p_s);
    cudaGetSymbolAddress((void**)&bm,   p_bm);
    cudaGetSymbolAddress((void**)&att,  p_att);
    cudaGetSymbolAddress((void**)&y,    p_y);
    cudaGetSymbolAddress((void**)&hb,   p_h);
    cudaGetSymbolAddress((void**)&x1,   p_x1);
    cudaGetSymbolAddress((void**)&x2,   p_x2);
    cudaGetSymbolAddress((void**)&mb,   g_m);
    cudaGetSymbolAddress((void**)&pinp, p_inp);
    cudaGetSymbolAddress((void**)&pw1,  p_wqkv1);
    cudaGetSymbolAddress((void**)&pw2,  p_wqkv2);
    cudaGetSymbolAddress((void**)&W1a,  p_W1a);
    cudaGetSymbolAddress((void**)&W2a,  p_W2a);
    cudaGetSymbolAddress((void**)&W1b,  p_W1b);
    cudaGetSymbolAddress((void**)&W2b,  p_W2b);
    cudaGetSymbolAddress((void**)&c1a,  p_c1w1);
    cudaGetSymbolAddress((void**)&c2a,  p_c2w1);
    cudaGetSymbolAddress((void**)&c1b,  p_c1w2);
    cudaGetSymbolAddress((void**)&c2b,  p_c2w2);
    cudaGetSymbolAddress((void**)&lw11, p_l1w1);
    cudaGetSymbolAddress((void**)&lw12, p_l1w2);
    cudaGetSymbolAddress((void**)&lw21, p_l2w1);
    cudaGetSymbolAddress((void**)&lw22, p_l2w2);

    cudaFuncSetAttribute(gemm_p<0,2,5>, cudaFuncAttributeMaxDynamicSharedMemorySize, SMEM_DYN);
    cudaFuncSetAttribute(gemm_p<0,0,5>, cudaFuncAttributeMaxDynamicSharedMemorySize, SMEM_DYN);
    cudaFuncSetAttribute(gemm_p<0,0,2>, cudaFuncAttributeMaxDynamicSharedMemorySize, SMEM_DYN);
    cudaFuncSetAttribute(gemm_p<2,2,2>, cudaFuncAttributeMaxDynamicSharedMemorySize, SMEM_DYN);
    cudaFuncSetAttribute(gemm_p<1,2,3>, cudaFuncAttributeMaxDynamicSharedMemorySize, SMEM_DYN);
    cudaFuncSetAttribute(gemm_p<2,0,5>, cudaFuncAttributeMaxDynamicSharedMemorySize, SMEM_DYN);
    cudaFuncSetAttribute(gemm_p<0,0,0>, cudaFuncAttributeMaxDynamicSharedMemorySize, SMEM_DYN);
    cudaFuncSetAttribute(gemm_p<0,0,1>, cudaFuncAttributeMaxDynamicSharedMemorySize, SMEM_DYN);
    cudaFuncSetAttribute(gemm_p<1,0,5>, cudaFuncAttributeMaxDynamicSharedMemorySize, SMEM_DYN);

    auto pkE = [&](const float* src, uint32_t* dst, ll n, bool relu) {
        const int n4 = (int)(n >> 2);
        const int gr = (n4 + 1023) / 1024;
        if (relu) pack_elem<true ><<<gr, 256>>>((const float4*)src, (uint4*)dst, n4);
        else      pack_elem<false><<<gr, 256>>>((const float4*)src, (uint4*)dst, n4);
    };
    auto pkP = [&](const float* src, uint32_t* dst, ll n, int C, bool relu) {
        const int n4 = (int)(n >> 2);
        const int gr = (n4 + 1023) / 1024;
        if (relu) pack_planar<true ><<<gr, 256>>>(src, dst, C, n4);
        else      pack_planar<false><<<gr, 256>>>(src, dst, C, n4);
    };

    const ll DS  = (ll)DD * SS;
    const ll DM  = (ll)DD * MIDD;
    const ll MS  = (ll)MIDD * SS;
    const ll SM  = (ll)SS * MIDD;
    const ll WSZ = (ll)HH * 3 * MIDD * SS;

    // ---- one-time packing of inputs & weights ----
    pkE(inp,    pinp,  DS, false);                      // element (transposed use)
    pkP(enc_k,  qkv2 + DS,       DS, SS, true);         // planar+relu (z-GEMM A)
    pkP(enc_v,  qkv2 + 2ll * DS, DS, SS, true);
    pkP(w_qkv1, pw1,  3ll * DD * DD, DD, false);
    pkP(w_qkv2, pw2,  (ll)DD * DD,   DD, false);
    pkP(mh1_W1, W1a,  WSZ, SS,   false);
    pkP(mh1_W2, W2a,  WSZ, MIDD, false);
    pkP(mh2_W1, W1b,  WSZ, SS,   false);
    pkP(mh2_W2, W2b,  WSZ, MIDD, false);
    pkP(c1_w1,  c1a,  (ll)MIDD * HH * DD, HH * DD, false);
    pkP(c2_w1,  c2a,  (ll)MIDD * HH * DD, HH * DD, false);
    pkP(c1_w2,  c1b,  (ll)DD * MIDD, MIDD, false);
    pkP(c2_w2,  c2b,  (ll)DD * MIDD, MIDD, false);
    pkP(l1_w1,  lw11, (ll)MIDD * SS,   SS,   false);
    pkP(l1_w2,  lw12, (ll)SOUT * MIDD, MIDD, false);
    pkP(l2_w1,  lw21, (ll)MIDD * SOUT, SOUT, false);
    pkP(l2_w2,  lw22, (ll)SOUT * MIDD, MIDD, false);

    auto run_block = [&](const uint32_t* qarr,
                         const uint32_t* W1, const uint32_t* W2,
                         const uint32_t* cw1, const uint32_t* cw2) {
        // merged z (grid.z=24): z[q,h] = relu(qarr[q]) @ W1[h,q]^T -> planar+relu
        gemm_p<0,0,5><<<dim3(MIDD / 128, DD / 128, 24), 256, SMEM_DYN>>>(
            qarr, W1, z,
            DD, MIDD, SS,
            0, 3ll * MS, DM,
            DS, MS, (ll)HH * DM);
        // merged s (grid.z=24): s[h,q] = relu(z[q,h]) @ W2[h,q]^T -> element
        gemm_p<0,0,2><<<dim3(SS / 128, DD / 128, 24), 256, SMEM_DYN>>>(
            z, W2, s,
            DD, SS, MIDD,
            DM, 3ll * SM, 3ll * DS,
            (ll)HH * DM, SM, DS);
        // b[h] = k^T q  (A = sk transposed, B = sq transposed) -> element
        gemm_p<2,2,2><<<dim3(SS / 128, SS / 128, HH), 256, SMEM_DYN>>>(
            s + DS, s, bm, SS, SS, DD, 3ll * DS, 3ll * DS, (ll)SS * SS, 0, 0, 0);
        // att[h] = v @ b  (A = sv element row-major, B = bm transposed) -> element+relu
        gemm_p<1,2,3><<<dim3(SS / 128, DD / 128, HH), 256, SMEM_DYN>>>(
            s + 2ll * DS, bm, att, DD, SS, SS, 3ll * DS, (ll)SS * SS, DS, 0, 0, 0);
        // y = relu(cat)^T @ cw1^T  (A = att transposed, B planar) -> planar+relu
        gemm_p<2,0,5><<<dim3(MIDD / 128, SS / 128, 1), 256, SMEM_DYN>>>(
            att, cw1, y, SS, MIDD, HH * DD, 0, 0, 0, 0, 0, 0);
        // m = cw2 @ relu(y)^T  (planar x planar) -> fp32
        gemm_p<0,0,0><<<dim3(SS / 128, DD / 128, 1), 256, SMEM_DYN>>>(
            cw2, y, mb, DD, SS, MIDD, 0, 0, 0, 0, 0, 0);
    };

    // qkv1[q] = w_qkv1[q] @ inp  (A planar, B = inp transposed) -> planar+relu
    gemm_p<0,2,5><<<dim3(SS / 128, DD / 128, 3), 256, SMEM_DYN>>>(
        pw1, pinp, qkv, DD, SS, DD, (ll)DD * DD, 0, DS, 0, 0, 0);

    run_block(qkv, W1a, W2a, c1a, c1b);
    add_ln_k<false><<<DD, 256>>>(inp, mb, gamma, beta, hb);   // h1 element plain

    // q2 = w_qkv2[0] @ h1  (A planar, B = hb element transposed) -> planar+relu
    gemm_p<0,2,5><<<dim3(SS / 128, DD / 128, 1), 256, SMEM_DYN>>>(
        pw2, hb, qkv2, DD, SS, DD, 0, 0, 0, 0, 0, 0);

    run_block(qkv2, W1b, W2b, c2a, c2b);
    add_ln_k<true><<<DD, 256>>>(inp, mb, gamma, beta, hb);    // h2 element+relu

    // x1 = relu(h2) @ l1_w1^T  (A element row-major, B planar) -> planar+relu
    gemm_p<1,0,5><<<dim3(MIDD / 128, DD / 128, 1), 256, SMEM_DYN>>>(
        hb, lw11, x1, DD, MIDD, SS, 0, 0, 0, 0, 0, 0);
    // x2 = relu(x1) @ l1_w2^T  (planar x planar) -> planar+relu
    gemm_p<0,0,5><<<dim3(SOUT / 128, DD / 128, 1), 256, SMEM_DYN>>>(
        x1, lw12, x2, DD, SOUT, MIDD, 0, 0, 0, 0, 0, 0);
    // y1 = relu(x2) @ l2_w1^T  (planar x planar) -> planar+relu (into x1)
    gemm_p<0,0,5><<<dim3(MIDD / 128, DD / 128, 1), 256, SMEM_DYN>>>(
        x2, lw21, x1, DD, MIDD, SOUT, 0, 0, 0, 0, 0, 0);
    // out = tanh(relu(y1) @ l2_w2^T)  -> fp32 + tanh
    gemm_p<0,0,1><<<dim3(SOUT / 128, DD / 128, 1), 256, SMEM_DYN>>>(
        x1, lw22, out, DD, SOUT, MIDD, 0, 0, 0, 0, 0, 0);
}

// round 17
// speedup vs baseline: 1.2478x; 1.2478x over previous
#include <cuda_runtime.h>
#include <cstdint>

#define HH 8
#define DD 1024
#define SS 1024
#define MIDD 2048
#define SOUT 512

typedef long long ll;

// ---------------- scratch (device globals; no allocation allowed) ----------
// element format: one uint32 per element = [hi_bf16 (low 2B) | lo_bf16 (hi 2B)]
__device__ uint32_t p_qkv [3ll * DD * SS];             // (q,d,s)
__device__ uint32_t p_qkv2[3ll * DD * SS];             // q2, enc_k, enc_v (q,d,s)
__device__ uint32_t p_z[3ll * HH * DD * MIDD];         // (q,h,d,m)
__device__ uint32_t p_s[3ll * HH * SS * DD];           // q0: sqT (h,t,d), q1: skT (h,t,d), q2: sv (h,d,s)
__device__ uint32_t p_bm[(ll)HH * SS * SS];            // bT (h,t,s)
__device__ uint32_t p_att[(ll)SS * HH * DD];           // attT (t, h*D+d)
__device__ uint32_t p_y[(ll)SS * MIDD];                // (t, m)
__device__ uint32_t p_h[(ll)DD * SS];                  // h2 (d,s)
__device__ uint32_t p_ht[(ll)SS * DD];                 // h1T (s,d)
__device__ uint32_t p_x1[(ll)DD * MIDD];
__device__ uint32_t p_x2[(ll)DD * SOUT];
__device__ float    g_m[(ll)DD * SS];                  // fp32 (d,s)
// packed inputs / weights (element format)
__device__ uint32_t p_inpT[(ll)SS * DD];               // inpT (s,d)
__device__ uint32_t p_wqkv1[3ll * DD * DD];
__device__ uint32_t p_wqkv2[(ll)DD * DD];
__device__ uint32_t p_W1a[(ll)HH * 3 * MIDD * SS];
__device__ uint32_t p_W2a[(ll)HH * 3 * SS * MIDD];
__device__ uint32_t p_W1b[(ll)HH * 3 * MIDD * SS];
__device__ uint32_t p_W2b[(ll)HH * 3 * SS * MIDD];
__device__ uint32_t p_c1w1[(ll)MIDD * HH * DD];
__device__ uint32_t p_c2w1[(ll)MIDD * HH * DD];
__device__ uint32_t p_c1w2[(ll)DD * MIDD];
__device__ uint32_t p_c2w2[(ll)DD * MIDD];
__device__ uint32_t p_l1w1[(ll)MIDD * SS];
__device__ uint32_t p_l1w2[(ll)SOUT * MIDD];
__device__ uint32_t p_l2w1[(ll)MIDD * SOUT];
__device__ uint32_t p_l2w2[(ll)SOUT * MIDD];

// ---------------- PTX helpers (base sm_103 features only) -------------------
__device__ __forceinline__ uint32_t smem_u32(const void* p) {
    uint32_t a;
    asm("{ .reg .u64 t; cvta.to.shared.u64 t, %1; cvt.u32.u64 %0, t; }"
        : "=r"(a) : "l"(p));
    return a;
}
__device__ __forceinline__ void cpa16(uint32_t dst, const void* src) {
    asm volatile("cp.async.cg.shared.global [%0], [%1], 16;"
                 :: "r"(dst), "l"(src) : "memory");
}
__device__ __forceinline__ void cp_commit() {
    asm volatile("cp.async.commit_group;" ::: "memory");
}
template<int NG>
__device__ __forceinline__ void cp_wait() {
    asm volatile("cp.async.wait_group %0;" :: "n"(NG) : "memory");
}
__device__ __forceinline__ uint32_t prmtb(uint32_t a, uint32_t b, uint32_t s) {
    uint32_t r;
    asm("prmt.b32 %0, %1, %2, %3;" : "=r"(r) : "r"(a), "r"(b), "r"(s));
    return r;
}

// pack two floats -> two element words ([hi|lo] each)
template<bool RELU>
__device__ __forceinline__ void pack2(float2 v, uint32_t& w0, uint32_t& w1) {
    if (RELU) { v.x = fmaxf(v.x, 0.f); v.y = fmaxf(v.y, 0.f); }
    uint32_t hp, lp;
    asm("cvt.rn.bf16x2.f32 %0, %1, %2;" : "=r"(hp) : "f"(v.y), "f"(v.x));
    const float hx = __uint_as_float(hp << 16);
    const float hy = __uint_as_float(hp & 0xffff0000u);
    asm("cvt.rn.bf16x2.f32 %0, %1, %2;" : "=r"(lp) : "f"(v.y - hy), "f"(v.x - hx));
    w0 = prmtb(hp, lp, 0x5410);
    w1 = prmtb(hp, lp, 0x7632);
}
template<bool RELU>
__device__ __forceinline__ uint32_t pack1(float x) {
    uint32_t a, b;
    pack2<RELU>(make_float2(x, x), a, b);
    return a;
}
// two adjacent element words -> bf16x2 hi-pair + lo-pair (2 PRMT)
__device__ __forceinline__ void fragp(const uint32_t* p, uint32_t& hi, uint32_t& lo) {
    const uint2 e = *(const uint2*)p;
    hi = prmtb(e.x, e.y, 0x5410);
    lo = prmtb(e.x, e.y, 0x7632);
}

__device__ __forceinline__ void mma16(float* d, const uint32_t* a, const uint32_t* b) {
    asm volatile(
        "mma.sync.aligned.m16n8k16.row.col.f32.bf16.bf16.f32 "
        "{%0,%1,%2,%3}, {%4,%5,%6,%7}, {%8,%9}, {%0,%1,%2,%3};"
        : "+f"(d[0]), "+f"(d[1]), "+f"(d[2]), "+f"(d[3])
        : "r"(a[0]), "r"(a[1]), "r"(a[2]), "r"(a[3]), "r"(b[0]), "r"(b[1]));
}

// ---------------- pack kernels ----------------------------------------------
template<bool RELU>
__global__ __launch_bounds__(256) void pack_elem(
    const float4* __restrict__ src, uint4* __restrict__ dst, int n4)
{
    const int base = blockIdx.x * 1024 + threadIdx.x;
    float4 v[4];
    #pragma unroll
    for (int j = 0; j < 4; j++) {
        const int i = base + j * 256;
        if (i < n4) v[j] = src[i];
    }
    #pragma unroll
    for (int j = 0; j < 4; j++) {
        const int i = base + j * 256;
        if (i < n4) {
            uint4 o;
            pack2<RELU>(make_float2(v[j].x, v[j].y), o.x, o.y);
            pack2<RELU>(make_float2(v[j].z, v[j].w), o.z, o.w);
            dst[i] = o;
        }
    }
}

// element transpose-pack: fp32 X[R][C] -> element Y[C][R]
__global__ __launch_bounds__(256) void pt_e(
    const float* __restrict__ X, uint32_t* __restrict__ Y, int R, int C)
{
    const int base = blockIdx.x * 1024 + threadIdx.x;
    #pragma unroll
    for (int j = 0; j < 4; j++) {
        const int idx = base + j * 256;
        if (idx < R * C) {
            const int r = idx / C, c = idx % C;
            Y[(ll)c * R + r] = pack1<false>(X[idx]);
        }
    }
}

// ---------------- packed bf16x3 mma.sync GEMM (row-major x row-major) -------
// D[m][n] = sum_k a[m][k] * b[n][k]; both operands element row-major.
//   EP: 0 fp32, 1 fp32+tanh, 2 element, 3 element+relu,
//       7 element transposed iff (qz<2) else normal,
//       8 element transposed + relu.
// Batch decode: h = bz & 7, q = bz >> 3. 256 threads (8 warps, 2x4 grid).

#define STR     40
#define TILE_W  (128 * STR)
#define STAGE_B (TILE_W * 4)
#define SMEM_DYN (4 * STAGE_B)

template<int EP>
__global__ __launch_bounds__(256, 2) void gemm_p(
    const uint32_t* __restrict__ Ag, const uint32_t* __restrict__ Bg, void* Cg,
    int M, int N, int K, int ldC,
    ll sA, ll sB, ll sC, ll sA2, ll sB2, ll sC2)
{
    extern __shared__ __align__(16) uint32_t smem[];
    const uint32_t sb = smem_u32(smem);

    const int bz = blockIdx.z;
    const int hz = bz & 7, qz = bz >> 3;
    const uint32_t* A = Ag + (ll)hz * sA + (ll)qz * sA2;
    const uint32_t* B = Bg + (ll)hz * sB + (ll)qz * sB2;
    const ll coff = (ll)hz * sC + (ll)qz * sC2;
    const int m0 = blockIdx.y * 128;
    const int n0 = blockIdx.x * 128;

    const int tid = threadIdx.x;
    const int wid = tid >> 5, lid = tid & 31;
    const int wm = wid >> 2, wn = wid & 3;
    const int g = lid >> 2, tg = lid & 3;

    float acc[4][4][4];
    #pragma unroll
    for (int mi = 0; mi < 4; mi++)
        #pragma unroll
        for (int ni = 0; ni < 4; ni++)
            #pragma unroll
            for (int r = 0; r < 4; r++) acc[mi][ni][r] = 0.f;

    auto issue = [&](int t) {
        const int st = t & 1;
        const uint32_t abase = sb + (uint32_t)(st * 2) * STAGE_B;
        const uint32_t bbase = abase + STAGE_B;
        const int k0 = t << 5;
        #pragma unroll
        for (int i = 0; i < 4; i++) {
            int idx = tid + i * 256;
            int r = idx >> 3, kq = (idx & 7) << 2;
            cpa16(abase + (uint32_t)(r * STR + kq) * 4,
                  A + (ll)(m0 + r) * K + k0 + kq);
        }
        #pragma unroll
        for (int i = 0; i < 4; i++) {
            int idx = tid + i * 256;
            int r = idx >> 3, kq = (idx & 7) << 2;
            cpa16(bbase + (uint32_t)(r * STR + kq) * 4,
                  B + (ll)(n0 + r) * K + k0 + kq);
        }
    };

    const int T = K >> 5;
    issue(0);
    cp_commit();

    for (int t = 0; t < T; t++) {
        if (t + 1 < T) { issue(t + 1); cp_commit(); cp_wait<1>(); }
        else           { cp_wait<0>(); }
        __syncthreads();

        const uint32_t* As = smem + (t & 1) * 2 * TILE_W;
        const uint32_t* Bs = As + TILE_W;

        #pragma unroll
        for (int ks = 0; ks < 2; ks++) {
            const int kb = ks * 16;
            uint32_t bh[4][2], bl[4][2];
            #pragma unroll
            for (int ni = 0; ni < 4; ni++) {
                const uint32_t* p = Bs + (wn * 32 + ni * 8 + g) * STR + kb + 2 * tg;
                fragp(p,     bh[ni][0], bl[ni][0]);
                fragp(p + 8, bh[ni][1], bl[ni][1]);
            }
            #pragma unroll
            for (int mi = 0; mi < 4; mi++) {
                uint32_t ah[4], al[4];
                const uint32_t* p = As + (wm * 64 + mi * 16 + g) * STR + kb + 2 * tg;
                fragp(p,               ah[0], al[0]);
                fragp(p + 8 * STR,     ah[1], al[1]);
                fragp(p + 8,           ah[2], al[2]);
                fragp(p + 8 * STR + 8, ah[3], al[3]);
                #pragma unroll
                for (int ni = 0; ni < 4; ni++) {
                    mma16(acc[mi][ni], ah, bh[ni]);
                    mma16(acc[mi][ni], ah, bl[ni]);
                    mma16(acc[mi][ni], al, bh[ni]);
                }
            }
        }
        __syncthreads();
    }

    // ---- epilogue ----
    #pragma unroll
    for (int mi = 0; mi < 4; mi++) {
        #pragma unroll
        for (int ni = 0; ni < 4; ni++) {
            const int r0 = m0 + wm * 64 + mi * 16 + g;
            const int c  = n0 + wn * 32 + ni * 8 + 2 * tg;
            float2 v0 = make_float2(acc[mi][ni][0], acc[mi][ni][1]);
            float2 v1 = make_float2(acc[mi][ni][2], acc[mi][ni][3]);
            if (EP <= 1) {
                float* C = (float*)Cg + coff;
                if (EP == 1) {
                    v0.x = tanhf(v0.x); v0.y = tanhf(v0.y);
                    v1.x = tanhf(v1.x); v1.y = tanhf(v1.y);
                }
                *(float2*)(C + (ll)r0 * ldC + c)       = v0;
                *(float2*)(C + (ll)(r0 + 8) * ldC + c) = v1;
            } else if (EP == 2 || EP == 3) {
                uint32_t* C = (uint32_t*)Cg + coff;
                uint2 w0, w1;
                pack2<EP == 3>(v0, w0.x, w0.y);
                pack2<EP == 3>(v1, w1.x, w1.y);
                *(uint2*)(C + (ll)r0 * ldC + c)       = w0;
                *(uint2*)(C + (ll)(r0 + 8) * ldC + c) = w1;
            } else {
                uint32_t* C = (uint32_t*)Cg + coff;
                uint2 w0, w1;
                pack2<EP == 8>(v0, w0.x, w0.y);
                pack2<EP == 8>(v1, w1.x, w1.y);
                const bool tr = (EP == 8) || (qz < 2);
                if (tr) {
                    C[(ll)c * ldC + r0]           = w0.x;
                    C[(ll)(c + 1) * ldC + r0]     = w0.y;
                    C[(ll)c * ldC + r0 + 8]       = w1.x;
                    C[(ll)(c + 1) * ldC + r0 + 8] = w1.y;
                } else {
                    *(uint2*)(C + (ll)r0 * ldC + c)       = w0;
                    *(uint2*)(C + (ll)(r0 + 8) * ldC + c) = w1;
                }
            }
        }
    }
}

// ---------------- fused residual-add + LayerNorm -> element packed -----------
// TR: write output transposed (s, d) instead of (d, s)
template<bool RELU, bool TR>
__global__ __launch_bounds__(256) void add_ln_k(
    const float* __restrict__ x, const float* __restrict__ m,
    const float* __restrict__ g, const float* __restrict__ b,
    uint32_t* __restrict__ o)
{
    const int row = blockIdx.x;
    const ll off = (ll)row * SS;
    float2 v[2];
    float sum = 0.f, sq = 0.f;
    #pragma unroll
    for (int j = 0; j < 2; j++) {
        int i2 = threadIdx.x * 2 + j * 512;
        float2 xv = *(const float2*)(x + off + i2);
        float2 mv = *(const float2*)(m + off + i2);
        v[j] = make_float2(xv.x + mv.x, xv.y + mv.y);
        sum += v[j].x + v[j].y;
        sq  += v[j].x * v[j].x + v[j].y * v[j].y;
    }
    #pragma unroll
    for (int o2 = 16; o2; o2 >>= 1) {
        sum += __shfl_xor_sync(0xffffffffu, sum, o2);
        sq  += __shfl_xor_sync(0xffffffffu, sq,  o2);
    }
    __shared__ float rs[8], rq[8];
    const int w = threadIdx.x >> 5, l = threadIdx.x & 31;
    if (l == 0) { rs[w] = sum; rq[w] = sq; }
    __syncthreads();
    if (w == 0) {
        float s2 = (l < 8) ? rs[l] : 0.f;
        float q2 = (l < 8) ? rq[l] : 0.f;
        #pragma unroll
        for (int o2 = 4; o2; o2 >>= 1) {
            s2 += __shfl_xor_sync(0xffffffffu, s2, o2);
            q2 += __shfl_xor_sync(0xffffffffu, q2, o2);
        }
        if (l == 0) { rs[0] = s2; rq[0] = q2; }
    }
    __syncthreads();
    const float mu  = rs[0] * (1.f / SS);
    const float var = rq[0] * (1.f / SS) - mu * mu;
    const float inv = rsqrtf(var + 1e-6f);
    #pragma unroll
    for (int j = 0; j < 2; j++) {
        int i2 = threadIdx.x * 2 + j * 512;
        float2 gv = *(const float2*)(g + i2);
        float2 bv = *(const float2*)(b + i2);
        float2 t = make_float2((v[j].x - mu) * inv * gv.x + bv.x,
                               (v[j].y - mu) * inv * gv.y + bv.y);
        uint2 wo;
        pack2<RELU>(t, wo.x, wo.y);
        if (TR) {
            o[(ll)i2 * DD + row]       = wo.x;
            o[(ll)(i2 + 1) * DD + row] = wo.y;
        } else {
            *(uint2*)(o + off + i2) = wo;
        }
    }
}

// ---------------- host orchestration ----------------------------------------
extern "C" void kernel_launch(void* const* d_in, const int* in_sizes, int n_in,
                              void* d_out, int out_size)
{
    const float* inp    = (const float*)d_in[0];
    const float* enc_k  = (const float*)d_in[1];
    const float* enc_v  = (const float*)d_in[2];
    const float* w_qkv1 = (const float*)d_in[3];
    const float* w_qkv2 = (const float*)d_in[4];
    const float* mh1_W1 = (const float*)d_in[5];
    const float* mh1_W2 = (const float*)d_in[6];
    const float* mh2_W1 = (const float*)d_in[7];
    const float* mh2_W2 = (const float*)d_in[8];
    const float* c1_w1  = (const float*)d_in[9];
    const float* c1_w2  = (const float*)d_in[10];
    const float* c2_w1  = (const float*)d_in[11];
    const float* c2_w2  = (const float*)d_in[12];
    const float* l1_w1  = (const float*)d_in[13];
    const float* l1_w2  = (const float*)d_in[14];
    const float* l2_w1  = (const float*)d_in[15];
    const float* l2_w2  = (const float*)d_in[16];
    const float* gamma  = (const float*)d_in[17];
    const float* beta   = (const float*)d_in[18];
    float* out = (float*)d_out;

    uint32_t *qkv, *qkv2, *z, *s, *bm, *att, *y, *hb, *hbt, *x1, *x2;
    uint32_t *pinpT, *pw1, *pw2;
    uint32_t *W1a, *W2a, *W1b, *W2b, *c1a, *c2a, *c1b, *c2b;
    uint32_t *lw11, *lw12, *lw21, *lw22;
    float* mb;
    cudaGetSymbolAddress((void**)&qkv,  p_qkv);
    cudaGetSymbolAddress((void**)&qkv2, p_qkv2);
    cudaGetSymbolAddress((void**)&z,    p_z);
    cudaGetSymbolAddress((void**)&s,    p_s);
    cudaGetSymbolAddress((void**)&bm,   p_bm);
    cudaGetSymbolAddress((void**)&att,  p_att);
    cudaGetSymbolAddress((void**)&y,    p_y);
    cudaGetSymbolAddress((void**)&hb,   p_h);
    cudaGetSymbolAddress((void**)&hbt,  p_ht);
    cudaGetSymbolAddress((void**)&x1,   p_x1);
    cudaGetSymbolAddress((void**)&x2,   p_x2);
    cudaGetSymbolAddress((void**)&mb,   g_m);
    cudaGetSymbolAddress((void**)&pinpT, p_inpT);
    cudaGetSymbolAddress((void**)&pw1,  p_wqkv1);
    cudaGetSymbolAddress((void**)&pw2,  p_wqkv2);
    cudaGetSymbolAddress((void**)&W1a,  p_W1a);
    cudaGetSymbolAddress((void**)&W2a,  p_W2a);
    cudaGetSymbolAddress((void**)&W1b,  p_W1b);
    cudaGetSymbolAddress((void**)&W2b,  p_W2b);
    cudaGetSymbolAddress((void**)&c1a,  p_c1w1);
    cudaGetSymbolAddress((void**)&c2a,  p_c2w1);
    cudaGetSymbolAddress((void**)&c1b,  p_c1w2);
    cudaGetSymbolAddress((void**)&c2b,  p_c2w2);
    cudaGetSymbolAddress((void**)&lw11, p_l1w1);
    cudaGetSymbolAddress((void**)&lw12, p_l1w2);
    cudaGetSymbolAddress((void**)&lw21, p_l2w1);
    cudaGetSymbolAddress((void**)&lw22, p_l2w2);

    cudaFuncSetAttribute(gemm_p<0>, cudaFuncAttributeMaxDynamicSharedMemorySize, SMEM_DYN);
    cudaFuncSetAttribute(gemm_p<1>, cudaFuncAttributeMaxDynamicSharedMemorySize, SMEM_DYN);
    cudaFuncSetAttribute(gemm_p<2>, cudaFuncAttributeMaxDynamicSharedMemorySize, SMEM_DYN);
    cudaFuncSetAttribute(gemm_p<3>, cudaFuncAttributeMaxDynamicSharedMemorySize, SMEM_DYN);
    cudaFuncSetAttribute(gemm_p<7>, cudaFuncAttributeMaxDynamicSharedMemorySize, SMEM_DYN);
    cudaFuncSetAttribute(gemm_p<8>, cudaFuncAttributeMaxDynamicSharedMemorySize, SMEM_DYN);

    auto pk = [&](const float* src, uint32_t* dst, ll n, bool relu) {
        const int n4 = (int)(n >> 2);
        const int gr = (n4 + 1023) / 1024;
        if (relu) pack_elem<true ><<<gr, 256>>>((const float4*)src, (uint4*)dst, n4);
        else      pack_elem<false><<<gr, 256>>>((const float4*)src, (uint4*)dst, n4);
    };

    const ll DS  = (ll)DD * SS;
    const ll DM  = (ll)DD * MIDD;
    const ll SD  = (ll)SS * DD;
    const ll MS  = (ll)MIDD * SS;
    const ll SM  = (ll)SS * MIDD;
    const ll WSZ = (ll)HH * 3 * MIDD * SS;
    const ll HSD = (ll)HH * SS * DD;
    const ll HDM = (ll)HH * DD * MIDD;

    // ---- one-time packing of inputs & weights ----
    pt_e<<<(int)((DS + 1023) / 1024), 256>>>(inp, pinpT, DD, SS);   // inpT (s,d)
    pk(enc_k,  qkv2 + DS,       DS, true);
    pk(enc_v,  qkv2 + 2ll * DS, DS, true);
    pk(w_qkv1, pw1,  3ll * DD * DD, false);
    pk(w_qkv2, pw2,  (ll)DD * DD,   false);
    pk(mh1_W1, W1a,  WSZ, false);
    pk(mh1_W2, W2a,  WSZ, false);
    pk(mh2_W1, W1b,  WSZ, false);
    pk(mh2_W2, W2b,  WSZ, false);
    pk(c1_w1,  c1a,  (ll)MIDD * HH * DD, false);
    pk(c2_w1,  c2a,  (ll)MIDD * HH * DD, false);
    pk(c1_w2,  c1b,  (ll)DD * MIDD, false);
    pk(c2_w2,  c2b,  (ll)DD * MIDD, false);
    pk(l1_w1,  lw11, (ll)MIDD * SS,   false);
    pk(l1_w2,  lw12, (ll)SOUT * MIDD, false);
    pk(l2_w1,  lw21, (ll)MIDD * SOUT, false);
    pk(l2_w2,  lw22, (ll)SOUT * MIDD, false);

    auto run_block = [&](const uint32_t* qarr,
                         const uint32_t* W1, const uint32_t* W2,
                         const uint32_t* cw1, const uint32_t* cw2) {
        // merged z (grid.z=24): z[q,h] = qarr[q] @ W1[h,q]^T -> element+relu
        gemm_p<3><<<dim3(MIDD / 128, DD / 128, 24), 256, SMEM_DYN>>>(
            qarr, W1, z,
            DD, MIDD, SS, MIDD,
            0, 3ll * MS, DM,
            DS, MS, HDM);
        // merged s (grid.z=24): s = z[q,h] @ W2[h,q]^T
        // q<2 -> transposed (t,d) into sqT/skT; q=2 -> normal (d,s) sv. EP=7.
        gemm_p<7><<<dim3(SS / 128, DD / 128, 24), 256, SMEM_DYN>>>(
            z, W2, s,
            DD, SS, MIDD, SS,
            DM, 3ll * SM, SD,
            HDM, SM, HSD);
        // bT[h][t][s] = sum_d sqT[t][d] * skT[s][d]  (row-major x row-major)
        gemm_p<2><<<dim3(SS / 128, SS / 128, HH), 256, SMEM_DYN>>>(
            s, s + HSD, bm, SS, SS, DD, SS,
            SD, SD, (ll)SS * SS, 0, 0, 0);
        // att[d][t] = sum_s sv[d][s] * bT[t][s] -> TRANSPOSED+relu into attT (t, h*D+d)
        gemm_p<8><<<dim3(SS / 128, DD / 128, HH), 256, SMEM_DYN>>>(
            s + 2ll * HSD, bm, att, DD, SS, SS, HH * DD,
            SD, (ll)SS * SS, DD, 0, 0, 0);
        // y[t][m] = sum_c attT[t][c] * cw1[m][c] -> element+relu
        gemm_p<3><<<dim3(MIDD / 128, SS / 128, 1), 256, SMEM_DYN>>>(
            att, cw1, y, SS, MIDD, HH * DD, MIDD, 0, 0, 0, 0, 0, 0);
        // m[d][t] = sum_m cw2[d][m] * y[t][m] -> fp32
        gemm_p<0><<<dim3(SS / 128, DD / 128, 1), 256, SMEM_DYN>>>(
            cw2, y, mb, DD, SS, MIDD, SS, 0, 0, 0, 0, 0, 0);
    };

    // qkv1[q][d][s] = sum_j w_qkv1[q][d][j] * inpT[s][j] -> element+relu
    gemm_p<3><<<dim3(SS / 128, DD / 128, 3), 256, SMEM_DYN>>>(
        pw1, pinpT, qkv, DD, SS, DD, SS, (ll)DD * DD, 0, DS, 0, 0, 0);

    run_block(qkv, W1a, W2a, c1a, c1b);
    add_ln_k<false, true><<<DD, 256>>>(inp, mb, gamma, beta, hbt);  // h1T (s,d)

    // q2[d][s] = sum_j w_qkv2[d][j] * h1T[s][j] -> element+relu
    gemm_p<3><<<dim3(SS / 128, DD / 128, 1), 256, SMEM_DYN>>>(
        pw2, hbt, qkv2, DD, SS, DD, SS, 0, 0, 0, 0, 0, 0);

    run_block(qkv2, W1b, W2b, c2a, c2b);
    add_ln_k<true, false><<<DD, 256>>>(inp, mb, gamma, beta, hb);   // h2 (d,s)+relu

    // x1 = relu(h2) @ l1_w1^T
    gemm_p<3><<<dim3(MIDD / 128, DD / 128, 1), 256, SMEM_DYN>>>(
        hb, lw11, x1, DD, MIDD, SS, MIDD, 0, 0, 0, 0, 0, 0);
    // x2 = relu(x1) @ l1_w2^T
    gemm_p<3><<<dim3(SOUT / 128, DD / 128, 1), 256, SMEM_DYN>>>(
        x1, lw12, x2, DD, SOUT, MIDD, SOUT, 0, 0, 0, 0, 0, 0);
    // y1 = relu(x2) @ l2_w1^T (into x1)
    gemm_p<3><<<dim3(MIDD / 128, DD / 128, 1), 256, SMEM_DYN>>>(
        x2, lw21, x1, DD, MIDD, SOUT, MIDD, 0, 0, 0, 0, 0, 0);
    // out = tanh(relu(y1) @ l2_w2^T) -> fp32 + tanh
    gemm_p<1><<<dim3(SOUT / 128, DD / 128, 1), 256, SMEM_DYN>>>(
        x1, lw22, out, DD, SOUT, MIDD, SOUT, 0, 0, 0, 0, 0, 0);
}